// round 1
// baseline (speedup 1.0000x reference)
#include <cuda_runtime.h>
#include <cuda_bf16.h>

#define N_NODES 50000
#define N_EDGES 600000
#define D_IN    256
#define D_OUT   128

// ---------------- scratch (static device globals; no allocation) ----------------
__device__ float g_x [N_NODES * D_OUT];   // after embed-linear
__device__ float g_y [N_NODES * D_OUT];   // gemm output (pre-aggregation)
__device__ float g_h [N_NODES * D_OUT];   // conv1 result
__device__ float g_dinv[N_NODES];
__device__ int   g_deg [N_NODES];
__device__ int   g_cur [N_NODES];
__device__ int   g_off [N_NODES + 1];
__device__ int   g_csr [N_EDGES];

// ---------------- small helpers ----------------
__global__ void k_zero() {
    int i = blockIdx.x * blockDim.x + threadIdx.x;
    if (i < N_NODES) { g_deg[i] = 0; g_cur[i] = 0; }
}

__global__ void k_count(const int* __restrict__ dst) {
    int e = blockIdx.x * blockDim.x + threadIdx.x;
    if (e < N_EDGES) atomicAdd(&g_deg[dst[e]], 1);
}

__global__ void k_dinv() {
    int i = blockIdx.x * blockDim.x + threadIdx.x;
    if (i < N_NODES) g_dinv[i] = rsqrtf((float)(g_deg[i] + 1));  // +1 self loop
}

// single-block exclusive scan of g_deg -> g_off
__global__ void k_scan() {
    __shared__ int sums[1024];
    const int t  = threadIdx.x;
    const int CH = (N_NODES + 1023) / 1024;     // 49
    int lo = t * CH;
    int hi = lo + CH; if (hi > N_NODES) hi = N_NODES;
    int s = 0;
    for (int i = lo; i < hi; i++) s += g_deg[i];
    sums[t] = s;
    __syncthreads();
    for (int d = 1; d < 1024; d <<= 1) {
        int v = (t >= d) ? sums[t - d] : 0;
        __syncthreads();
        sums[t] += v;
        __syncthreads();
    }
    int run = (t == 0) ? 0 : sums[t - 1];
    for (int i = lo; i < hi; i++) { g_off[i] = run; run += g_deg[i]; }
    if (t == 1023) g_off[N_NODES] = sums[1023];
}

__global__ void k_fill(const int* __restrict__ src, const int* __restrict__ dst) {
    int e = blockIdx.x * blockDim.x + threadIdx.x;
    if (e < N_EDGES) {
        int d = dst[e];
        int pos = g_off[d] + atomicAdd(&g_cur[d], 1);
        g_csr[pos] = src[e];
    }
}

// ---------------- node GEMM: out[n][j] = sum_k A[n][k] * W[j][k] (+bias) ----------------
// Block: 32 nodes x 128 output cols, 128 threads (thread = col j).
template<int K, bool RELU, bool GATHER>
__global__ void __launch_bounds__(128)
k_gemm(const float* __restrict__ A, const int* __restrict__ tokens,
       const float* __restrict__ W, const float* __restrict__ bias,
       float* __restrict__ out)
{
    constexpr int K4 = K / 4;
    __shared__ float4 As[32 * K4];
    const int tid = threadIdx.x;
    const int n0  = blockIdx.x * 32;

    // load A tile (gathered rows if GATHER), clamp row to avoid OOB
    for (int idx = tid; idx < 32 * K4; idx += 128) {
        int m  = idx / K4;
        int k4 = idx % K4;
        int nm = n0 + m; if (nm >= N_NODES) nm = N_NODES - 1;
        int row = GATHER ? tokens[nm] : nm;
        float4 v = ((const float4*)A)[row * K4 + k4];
        if (RELU) {
            v.x = fmaxf(v.x, 0.f); v.y = fmaxf(v.y, 0.f);
            v.z = fmaxf(v.z, 0.f); v.w = fmaxf(v.w, 0.f);
        }
        As[m * K4 + k4] = v;
    }
    __syncthreads();

    const int j = tid;
    float acc[32];
    #pragma unroll
    for (int m = 0; m < 32; m++) acc[m] = 0.f;

    constexpr int NCHUNK = K / 64;   // 64-wide K chunks held in regs
    #pragma unroll
    for (int c = 0; c < NCHUNK; c++) {
        float4 wreg[16];
        #pragma unroll
        for (int i = 0; i < 16; i++)
            wreg[i] = ((const float4*)W)[j * K4 + c * 16 + i];
        #pragma unroll
        for (int m = 0; m < 32; m++) {
            float s = 0.f;
            #pragma unroll
            for (int i = 0; i < 16; i++) {
                float4 a = As[m * K4 + c * 16 + i];
                s += a.x * wreg[i].x + a.y * wreg[i].y
                   + a.z * wreg[i].z + a.w * wreg[i].w;
            }
            acc[m] += s;
        }
    }

    float bj = bias ? bias[j] : 0.f;
    #pragma unroll
    for (int m = 0; m < 32; m++) {
        int nm = n0 + m;
        if (nm < N_NODES) out[nm * D_OUT + j] = acc[m] + bj;
    }
}

// ---------------- gather-style GCN aggregation ----------------
// warp per node; lane owns a float4 slice of the 128-wide row.
// out[n] = bias + dinv[n] * ( y[n]*dinv[n] + sum_{s in in(n)} y[s]*dinv[s] )
__global__ void k_conv(const float* __restrict__ y, const float* __restrict__ bias,
                       float* __restrict__ out)
{
    int gw   = (blockIdx.x * blockDim.x + threadIdx.x) >> 5;
    int lane = threadIdx.x & 31;
    if (gw >= N_NODES) return;

    const float4* y4 = (const float4*)y;
    float di = g_dinv[gw];
    float4 acc = y4[gw * 32 + lane];
    acc.x *= di; acc.y *= di; acc.z *= di; acc.w *= di;   // self loop (one dinv factored out)

    int b = g_off[gw], e = g_off[gw + 1];
    for (int i = b; i < e; i++) {
        int s = g_csr[i];
        float ds = g_dinv[s];
        float4 v = y4[s * 32 + lane];
        acc.x += v.x * ds; acc.y += v.y * ds;
        acc.z += v.z * ds; acc.w += v.w * ds;
    }

    float4 bb = ((const float4*)bias)[lane];
    float4 o;
    o.x = acc.x * di + bb.x; o.y = acc.y * di + bb.y;
    o.z = acc.z * di + bb.z; o.w = acc.w * di + bb.w;
    ((float4*)out)[gw * 32 + lane] = o;
}

// ---------------- launch ----------------
extern "C" void kernel_launch(void* const* d_in, const int* in_sizes, int n_in,
                              void* d_out, int out_size)
{
    const int*   tokens = (const int*)  d_in[0];
    const int*   eidx   = (const int*)  d_in[1];
    const float* embed  = (const float*)d_in[2];
    const float* Wn     = (const float*)d_in[3];
    const float* Wb     = (const float*)d_in[4];
    const float* w1     = (const float*)d_in[5];
    const float* b1     = (const float*)d_in[6];
    const float* w2     = (const float*)d_in[7];
    const float* b2     = (const float*)d_in[8];
    float* out = (float*)d_out;

    const int* src = eidx;
    const int* dst = eidx + N_EDGES;

    float *xp, *yp, *hp;
    cudaGetSymbolAddress((void**)&xp, g_x);
    cudaGetSymbolAddress((void**)&yp, g_y);
    cudaGetSymbolAddress((void**)&hp, g_h);

    const int NB_N = (N_NODES + 255) / 256;
    const int NB_E = (N_EDGES + 255) / 256;
    const int NB_G = (N_NODES + 31) / 32;          // gemm blocks (32 nodes each)
    const int NB_C = (N_NODES * 32 + 255) / 256;   // conv blocks (warp/node)

    // graph structure (recomputed every call; deterministic work)
    k_zero <<<NB_N, 256>>>();
    k_count<<<NB_E, 256>>>(dst);
    k_dinv <<<NB_N, 256>>>();
    k_scan <<<1, 1024>>>();
    k_fill <<<NB_E, 256>>>(src, dst);

    // embed + first linear (+ bias)
    k_gemm<D_IN, false, true ><<<NB_G, 128>>>(embed, tokens, Wn, Wb, xp);

    // conv1
    k_gemm<D_OUT, false, false><<<NB_G, 128>>>(xp, nullptr, w1, nullptr, yp);
    k_conv<<<NB_C, 256>>>(yp, b1, hp);

    // conv2 (relu fused into A load)
    k_gemm<D_OUT, true, false><<<NB_G, 128>>>(hp, nullptr, w2, nullptr, yp);
    k_conv<<<NB_C, 256>>>(yp, b2, out);
}

// round 3
// speedup vs baseline: 2.7152x; 2.7152x over previous
#include <cuda_runtime.h>
#include <cuda_bf16.h>
#include <cstdint>

#define N_NODES 50000
#define N_EDGES 600000
#define D_IN    256
#define D_OUT   128

// ---------------- scratch (static device globals; no allocation) ----------------
__device__ float g_x [N_NODES * D_OUT];   // after embed-linear
__device__ float g_y [N_NODES * D_OUT];   // gemm output (pre-aggregation)
__device__ float g_h [N_NODES * D_OUT];   // conv1 result
__device__ float g_dinv[N_NODES];
__device__ int   g_deg [N_NODES];
__device__ int   g_cur [N_NODES];
__device__ int   g_off [N_NODES + 1];
__device__ int   g_bsum [256];
__device__ int   g_bbase[256];
__device__ int   g_csr [N_EDGES];

// ---------------- graph-structure kernels ----------------
__global__ void k_zero() {
    int i = blockIdx.x * blockDim.x + threadIdx.x;
    if (i < N_NODES) { g_deg[i] = 0; g_cur[i] = 0; }
}
__global__ void k_count(const int* __restrict__ dst) {
    int e = blockIdx.x * blockDim.x + threadIdx.x;
    if (e < N_EDGES) atomicAdd(&g_deg[dst[e]], 1);
}
__global__ void k_dinv() {
    int i = blockIdx.x * blockDim.x + threadIdx.x;
    if (i < N_NODES) g_dinv[i] = rsqrtf((float)(g_deg[i] + 1));  // +1 self loop
}
// 3-phase parallel scan of g_deg -> g_off (exclusive)
__global__ void k_scan1() {
    __shared__ int s[256];
    int i = blockIdx.x * 256 + threadIdx.x;
    int v = (i < N_NODES) ? g_deg[i] : 0;
    s[threadIdx.x] = v; __syncthreads();
    for (int d = 128; d > 0; d >>= 1) {
        if (threadIdx.x < d) s[threadIdx.x] += s[threadIdx.x + d];
        __syncthreads();
    }
    if (threadIdx.x == 0) g_bsum[blockIdx.x] = s[0];
}
__global__ void k_scan2(int nblk) {
    __shared__ int s[256];
    int t = threadIdx.x;
    int v = (t < nblk) ? g_bsum[t] : 0;
    s[t] = v; __syncthreads();
    for (int d = 1; d < 256; d <<= 1) {
        int u = (t >= d) ? s[t - d] : 0;
        __syncthreads(); s[t] += u; __syncthreads();
    }
    g_bbase[t] = s[t] - v;
    if (t == 0) g_off[N_NODES] = N_EDGES;
}
__global__ void k_scan3() {
    __shared__ int s[256];
    int t = threadIdx.x;
    int i = blockIdx.x * 256 + t;
    int v = (i < N_NODES) ? g_deg[i] : 0;
    s[t] = v; __syncthreads();
    for (int d = 1; d < 256; d <<= 1) {
        int u = (t >= d) ? s[t - d] : 0;
        __syncthreads(); s[t] += u; __syncthreads();
    }
    if (i < N_NODES) g_off[i] = g_bbase[blockIdx.x] + s[t] - v;
}
__global__ void k_fill(const int* __restrict__ src, const int* __restrict__ dst) {
    int e = blockIdx.x * blockDim.x + threadIdx.x;
    if (e < N_EDGES) {
        int d = dst[e];
        int pos = g_off[d] + atomicAdd(&g_cur[d], 1);
        g_csr[pos] = src[e];
    }
}

// ---------------- tensor-core GEMM via mma.sync (bf16 split, fp32 accum) ----------------
// out[n][j] = sum_k A[n][k] * W[j][k] (+bias).  CTA: 128 rows x 128 cols, 256 thr.
// Warp grid 4(M) x 2(N); warp tile 32x64 -> 2x8 m16n8k16 tiles, 3-pass hi/lo split.
#define KCH   32                      // K chunk
#define SROW  36                      // padded smem row stride in bf16 (conflict-free)

__device__ __forceinline__ void mma16816(float* d, uint32_t a0, uint32_t a1,
                                         uint32_t a2, uint32_t a3,
                                         uint32_t b0, uint32_t b1) {
    asm volatile(
        "mma.sync.aligned.m16n8k16.row.col.f32.bf16.bf16.f32 "
        "{%0,%1,%2,%3}, {%4,%5,%6,%7}, {%8,%9}, {%0,%1,%2,%3};"
        : "+f"(d[0]), "+f"(d[1]), "+f"(d[2]), "+f"(d[3])
        : "r"(a0), "r"(a1), "r"(a2), "r"(a3), "r"(b0), "r"(b1));
}

__device__ __forceinline__ uint32_t pack_hi(float x, float y) {
    __nv_bfloat162 h = __floats2bfloat162_rn(x, y);
    return *(uint32_t*)&h;
}

template<int K, bool GATHER, bool RELU>
__global__ void __launch_bounds__(256)
k_gemm_mma(const float* __restrict__ A, const int* __restrict__ tokens,
           const float* __restrict__ W, const float* __restrict__ bias,
           float* __restrict__ out)
{
    __shared__ __align__(16) uint32_t sm[4 * 128 * (SROW / 2)];   // Ah, Al, Wh, Wl (uint32 = 2 bf16)
    uint32_t* sAh = sm;
    uint32_t* sAl = sm + 128 * (SROW / 2);
    uint32_t* sWh = sm + 2 * 128 * (SROW / 2);
    uint32_t* sWl = sm + 3 * 128 * (SROW / 2);

    const int tid  = threadIdx.x;
    const int wid  = tid >> 5;
    const int lane = tid & 31;
    const int wm   = wid >> 1;            // 0..3
    const int wn   = wid & 1;             // 0..1
    const int m_base = wm * 32;
    const int n_base = wn * 64;
    const int n0   = blockIdx.x * 128;

    const int qr = lane >> 2;             // 0..7
    const int qj = lane & 3;              // 0..3

    float acc[2][8][4];
    #pragma unroll
    for (int mt = 0; mt < 2; mt++)
        #pragma unroll
        for (int nt = 0; nt < 8; nt++)
            #pragma unroll
            for (int q = 0; q < 4; q++) acc[mt][nt][q] = 0.f;

    constexpr int K4 = K / 4;
    constexpr int NCH = K / KCH;

    for (int c = 0; c < NCH; c++) {
        // ---- load + split: A and W, 128 rows x 32 cols each (1024 float4 apiece) ----
        #pragma unroll
        for (int it = 0; it < 4; it++) {
            int i   = it * 256 + tid;
            int row = i >> 3;             // 0..127
            int f4  = i & 7;              // 0..7
            // A
            int node = n0 + row; if (node >= N_NODES) node = N_NODES - 1;
            int arow = GATHER ? __ldg(&tokens[node]) : node;
            float4 av = ((const float4*)A)[(size_t)arow * K4 + c * 8 + f4];
            if (RELU) {
                av.x = fmaxf(av.x, 0.f); av.y = fmaxf(av.y, 0.f);
                av.z = fmaxf(av.z, 0.f); av.w = fmaxf(av.w, 0.f);
            }
            float4 wv = ((const float4*)W)[(size_t)row * K4 + c * 8 + f4];
            int wbase = row * (SROW / 2) + f4 * 2;
            {
                uint32_t h0 = pack_hi(av.x, av.y), h1 = pack_hi(av.z, av.w);
                __nv_bfloat162 hh0 = *(__nv_bfloat162*)&h0;
                __nv_bfloat162 hh1 = *(__nv_bfloat162*)&h1;
                uint32_t l0 = pack_hi(av.x - __bfloat162float(hh0.x), av.y - __bfloat162float(hh0.y));
                uint32_t l1 = pack_hi(av.z - __bfloat162float(hh1.x), av.w - __bfloat162float(hh1.y));
                sAh[wbase] = h0; sAh[wbase + 1] = h1;
                sAl[wbase] = l0; sAl[wbase + 1] = l1;
            }
            {
                uint32_t h0 = pack_hi(wv.x, wv.y), h1 = pack_hi(wv.z, wv.w);
                __nv_bfloat162 hh0 = *(__nv_bfloat162*)&h0;
                __nv_bfloat162 hh1 = *(__nv_bfloat162*)&h1;
                uint32_t l0 = pack_hi(wv.x - __bfloat162float(hh0.x), wv.y - __bfloat162float(hh0.y));
                uint32_t l1 = pack_hi(wv.z - __bfloat162float(hh1.x), wv.w - __bfloat162float(hh1.y));
                sWh[wbase] = h0; sWh[wbase + 1] = h1;
                sWl[wbase] = l0; sWl[wbase + 1] = l1;
            }
        }
        __syncthreads();

        // ---- 2 k16 steps per chunk ----
        #pragma unroll
        for (int ks = 0; ks < 2; ks++) {
            const int kw = ks * 8 + qj;   // word offset within row
            uint32_t ah[2][4], al[2][4];
            #pragma unroll
            for (int mt = 0; mt < 2; mt++) {
                int r0 = (m_base + mt * 16 + qr) * (SROW / 2);
                int r1 = (m_base + mt * 16 + qr + 8) * (SROW / 2);
                ah[mt][0] = sAh[r0 + kw];     ah[mt][1] = sAh[r1 + kw];
                ah[mt][2] = sAh[r0 + kw + 4]; ah[mt][3] = sAh[r1 + kw + 4];
                al[mt][0] = sAl[r0 + kw];     al[mt][1] = sAl[r1 + kw];
                al[mt][2] = sAl[r0 + kw + 4]; al[mt][3] = sAl[r1 + kw + 4];
            }
            #pragma unroll
            for (int nt = 0; nt < 8; nt++) {
                int nr = (n_base + nt * 8 + qr) * (SROW / 2);
                uint32_t bh0 = sWh[nr + kw], bh1 = sWh[nr + kw + 4];
                uint32_t bl0 = sWl[nr + kw], bl1 = sWl[nr + kw + 4];
                #pragma unroll
                for (int mt = 0; mt < 2; mt++) {
                    mma16816(acc[mt][nt], ah[mt][0], ah[mt][1], ah[mt][2], ah[mt][3], bh0, bh1);
                    mma16816(acc[mt][nt], ah[mt][0], ah[mt][1], ah[mt][2], ah[mt][3], bl0, bl1);
                    mma16816(acc[mt][nt], al[mt][0], al[mt][1], al[mt][2], al[mt][3], bh0, bh1);
                }
            }
        }
        __syncthreads();
    }

    // ---- epilogue ----
    #pragma unroll
    for (int nt = 0; nt < 8; nt++) {
        int col = n_base + nt * 8 + qj * 2;
        float b0 = bias ? bias[col]     : 0.f;
        float b1 = bias ? bias[col + 1] : 0.f;
        #pragma unroll
        for (int mt = 0; mt < 2; mt++) {
            int r = n0 + m_base + mt * 16 + qr;
            if (r < N_NODES) {
                float2 v = { acc[mt][nt][0] + b0, acc[mt][nt][1] + b1 };
                *(float2*)(out + (size_t)r * D_OUT + col) = v;
            }
            if (r + 8 < N_NODES) {
                float2 v = { acc[mt][nt][2] + b0, acc[mt][nt][3] + b1 };
                *(float2*)(out + (size_t)(r + 8) * D_OUT + col) = v;
            }
        }
    }
}

// ---------------- gather-style GCN aggregation ----------------
__global__ void k_conv(const float* __restrict__ y, const float* __restrict__ bias,
                       float* __restrict__ out)
{
    int gw   = (blockIdx.x * blockDim.x + threadIdx.x) >> 5;
    int lane = threadIdx.x & 31;
    if (gw >= N_NODES) return;

    const float4* y4 = (const float4*)y;
    float di = g_dinv[gw];
    float4 acc = y4[gw * 32 + lane];
    acc.x *= di; acc.y *= di; acc.z *= di; acc.w *= di;   // self loop

    int b = g_off[gw], e = g_off[gw + 1];
    for (int i = b; i < e; i++) {
        int s = g_csr[i];
        float ds = g_dinv[s];
        float4 v = y4[s * 32 + lane];
        acc.x += v.x * ds; acc.y += v.y * ds;
        acc.z += v.z * ds; acc.w += v.w * ds;
    }

    float4 bb = ((const float4*)bias)[lane];
    float4 o;
    o.x = acc.x * di + bb.x; o.y = acc.y * di + bb.y;
    o.z = acc.z * di + bb.z; o.w = acc.w * di + bb.w;
    ((float4*)out)[gw * 32 + lane] = o;
}

// ---------------- launch ----------------
extern "C" void kernel_launch(void* const* d_in, const int* in_sizes, int n_in,
                              void* d_out, int out_size)
{
    const int*   tokens = (const int*)  d_in[0];
    const int*   eidx   = (const int*)  d_in[1];
    const float* embed  = (const float*)d_in[2];
    const float* Wn     = (const float*)d_in[3];
    const float* Wb     = (const float*)d_in[4];
    const float* w1     = (const float*)d_in[5];
    const float* b1     = (const float*)d_in[6];
    const float* w2     = (const float*)d_in[7];
    const float* b2     = (const float*)d_in[8];
    float* out = (float*)d_out;

    const int* src = eidx;
    const int* dst = eidx + N_EDGES;

    float *xp, *yp, *hp;
    cudaGetSymbolAddress((void**)&xp, g_x);
    cudaGetSymbolAddress((void**)&yp, g_y);
    cudaGetSymbolAddress((void**)&hp, g_h);

    const int NB_N = (N_NODES + 255) / 256;       // 196
    const int NB_E = (N_EDGES + 255) / 256;
    const int NB_G = (N_NODES + 127) / 128;       // 391
    const int NB_C = (N_NODES * 32 + 255) / 256;

    // graph structure
    k_zero <<<NB_N, 256>>>();
    k_count<<<NB_E, 256>>>(dst);
    k_dinv <<<NB_N, 256>>>();
    k_scan1<<<NB_N, 256>>>();
    k_scan2<<<1,    256>>>(NB_N);
    k_scan3<<<NB_N, 256>>>();
    k_fill <<<NB_E, 256>>>(src, dst);

    // embed + first linear (+ bias)
    k_gemm_mma<D_IN, true,  false><<<NB_G, 256>>>(embed, tokens, Wn, Wb, xp);
    // conv1
    k_gemm_mma<D_OUT, false, false><<<NB_G, 256>>>(xp, nullptr, w1, nullptr, yp);
    k_conv<<<NB_C, 256>>>(yp, b1, hp);
    // conv2 (relu fused into A load)
    k_gemm_mma<D_OUT, false, true ><<<NB_G, 256>>>(hp, nullptr, w2, nullptr, yp);
    k_conv<<<NB_C, 256>>>(yp, b2, out);
}

// round 4
// speedup vs baseline: 2.8109x; 1.0352x over previous
#include <cuda_runtime.h>
#include <cuda_bf16.h>
#include <cstdint>

#define N_NODES 50000
#define N_EDGES 600000
#define D_IN    256
#define D_OUT   128

// ---------------- scratch (static device globals; no allocation) ----------------
__device__ float g_x [N_NODES * D_OUT];   // prescaled linear output / agg input
__device__ float g_y [N_NODES * D_OUT];   // aggregated (unscaled) features
__device__ float g_h [N_NODES * D_OUT];   // relu+prescaled hidden
__device__ float g_dinv[N_NODES];
__device__ int   g_deg [N_NODES];
__device__ int   g_cur [N_NODES];
__device__ int   g_off [N_NODES + 1];
__device__ int   g_bsum [256];
__device__ int   g_bbase[256];
__device__ int   g_csr [N_EDGES];

// ---------------- graph-structure kernels ----------------
__global__ void k_zero() {
    int i = blockIdx.x * blockDim.x + threadIdx.x;
    if (i < N_NODES) { g_deg[i] = 0; g_cur[i] = 0; }
}
__global__ void k_count(const int* __restrict__ dst) {
    int e = blockIdx.x * blockDim.x + threadIdx.x;
    if (e < N_EDGES) atomicAdd(&g_deg[dst[e]], 1);
}
// 3-phase parallel scan of g_deg -> g_off (exclusive); dinv fused into phase 1
__global__ void k_scan1() {
    __shared__ int s[256];
    int i = blockIdx.x * 256 + threadIdx.x;
    int v = (i < N_NODES) ? g_deg[i] : 0;
    if (i < N_NODES) g_dinv[i] = rsqrtf((float)(v + 1));   // +1 self loop
    s[threadIdx.x] = v; __syncthreads();
    for (int d = 128; d > 0; d >>= 1) {
        if (threadIdx.x < d) s[threadIdx.x] += s[threadIdx.x + d];
        __syncthreads();
    }
    if (threadIdx.x == 0) g_bsum[blockIdx.x] = s[0];
}
__global__ void k_scan2(int nblk) {
    __shared__ int s[256];
    int t = threadIdx.x;
    int v = (t < nblk) ? g_bsum[t] : 0;
    s[t] = v; __syncthreads();
    for (int d = 1; d < 256; d <<= 1) {
        int u = (t >= d) ? s[t - d] : 0;
        __syncthreads(); s[t] += u; __syncthreads();
    }
    g_bbase[t] = s[t] - v;
    if (t == 0) g_off[N_NODES] = N_EDGES;
}
__global__ void k_scan3() {
    __shared__ int s[256];
    int t = threadIdx.x;
    int i = blockIdx.x * 256 + t;
    int v = (i < N_NODES) ? g_deg[i] : 0;
    s[t] = v; __syncthreads();
    for (int d = 1; d < 256; d <<= 1) {
        int u = (t >= d) ? s[t - d] : 0;
        __syncthreads(); s[t] += u; __syncthreads();
    }
    if (i < N_NODES) g_off[i] = g_bbase[blockIdx.x] + s[t] - v;
}
__global__ void k_fill(const int* __restrict__ src, const int* __restrict__ dst) {
    int e = blockIdx.x * blockDim.x + threadIdx.x;
    if (e < N_EDGES) {
        int d = dst[e];
        int pos = g_off[d] + atomicAdd(&g_cur[d], 1);
        g_csr[pos] = src[e];
    }
}

// ---------------- tensor-core GEMM via mma.sync (bf16 split, fp32 accum) ----------------
// out[n][j] = sum_k A[n][k] * W[j][k] + bias[j]; optional relu; optional *dinv[n].
// CTA: 128 rows x 128 cols, 256 thr. Warp grid 4(M) x 2(N); warp tile 32x64.
#define KCH   32
#define SROW  36                      // padded smem row stride in bf16

__device__ __forceinline__ void mma16816(float* d, uint32_t a0, uint32_t a1,
                                         uint32_t a2, uint32_t a3,
                                         uint32_t b0, uint32_t b1) {
    asm volatile(
        "mma.sync.aligned.m16n8k16.row.col.f32.bf16.bf16.f32 "
        "{%0,%1,%2,%3}, {%4,%5,%6,%7}, {%8,%9}, {%0,%1,%2,%3};"
        : "+f"(d[0]), "+f"(d[1]), "+f"(d[2]), "+f"(d[3])
        : "r"(a0), "r"(a1), "r"(a2), "r"(a3), "r"(b0), "r"(b1));
}

__device__ __forceinline__ uint32_t pack_hi(float x, float y) {
    __nv_bfloat162 h = __floats2bfloat162_rn(x, y);
    return *(uint32_t*)&h;
}

template<int K, bool GATHER, bool RELU_OUT, bool SCALE>
__global__ void __launch_bounds__(256)
k_gemm_mma(const float* __restrict__ A, const int* __restrict__ tokens,
           const float* __restrict__ W, const float* __restrict__ bias,
           float* __restrict__ out)
{
    __shared__ __align__(16) uint32_t sm[4 * 128 * (SROW / 2)];   // Ah, Al, Wh, Wl
    uint32_t* sAh = sm;
    uint32_t* sAl = sm + 128 * (SROW / 2);
    uint32_t* sWh = sm + 2 * 128 * (SROW / 2);
    uint32_t* sWl = sm + 3 * 128 * (SROW / 2);

    const int tid  = threadIdx.x;
    const int wid  = tid >> 5;
    const int lane = tid & 31;
    const int wm   = wid >> 1;
    const int wn   = wid & 1;
    const int m_base = wm * 32;
    const int n_base = wn * 64;
    const int n0   = blockIdx.x * 128;

    const int qr = lane >> 2;
    const int qj = lane & 3;

    float acc[2][8][4];
    #pragma unroll
    for (int mt = 0; mt < 2; mt++)
        #pragma unroll
        for (int nt = 0; nt < 8; nt++)
            #pragma unroll
            for (int q = 0; q < 4; q++) acc[mt][nt][q] = 0.f;

    constexpr int K4 = K / 4;
    constexpr int NCH = K / KCH;

    for (int c = 0; c < NCH; c++) {
        #pragma unroll
        for (int it = 0; it < 4; it++) {
            int i   = it * 256 + tid;
            int row = i >> 3;
            int f4  = i & 7;
            int node = n0 + row; if (node >= N_NODES) node = N_NODES - 1;
            int arow = GATHER ? __ldg(&tokens[node]) : node;
            float4 av = ((const float4*)A)[(size_t)arow * K4 + c * 8 + f4];
            float4 wv = ((const float4*)W)[(size_t)row * K4 + c * 8 + f4];
            int wbase = row * (SROW / 2) + f4 * 2;
            {
                uint32_t h0 = pack_hi(av.x, av.y), h1 = pack_hi(av.z, av.w);
                __nv_bfloat162 hh0 = *(__nv_bfloat162*)&h0;
                __nv_bfloat162 hh1 = *(__nv_bfloat162*)&h1;
                uint32_t l0 = pack_hi(av.x - __bfloat162float(hh0.x), av.y - __bfloat162float(hh0.y));
                uint32_t l1 = pack_hi(av.z - __bfloat162float(hh1.x), av.w - __bfloat162float(hh1.y));
                sAh[wbase] = h0; sAh[wbase + 1] = h1;
                sAl[wbase] = l0; sAl[wbase + 1] = l1;
            }
            {
                uint32_t h0 = pack_hi(wv.x, wv.y), h1 = pack_hi(wv.z, wv.w);
                __nv_bfloat162 hh0 = *(__nv_bfloat162*)&h0;
                __nv_bfloat162 hh1 = *(__nv_bfloat162*)&h1;
                uint32_t l0 = pack_hi(wv.x - __bfloat162float(hh0.x), wv.y - __bfloat162float(hh0.y));
                uint32_t l1 = pack_hi(wv.z - __bfloat162float(hh1.x), wv.w - __bfloat162float(hh1.y));
                sWh[wbase] = h0; sWh[wbase + 1] = h1;
                sWl[wbase] = l0; sWl[wbase + 1] = l1;
            }
        }
        __syncthreads();

        #pragma unroll
        for (int ks = 0; ks < 2; ks++) {
            const int kw = ks * 8 + qj;
            uint32_t ah[2][4], al[2][4];
            #pragma unroll
            for (int mt = 0; mt < 2; mt++) {
                int r0 = (m_base + mt * 16 + qr) * (SROW / 2);
                int r1 = (m_base + mt * 16 + qr + 8) * (SROW / 2);
                ah[mt][0] = sAh[r0 + kw];     ah[mt][1] = sAh[r1 + kw];
                ah[mt][2] = sAh[r0 + kw + 4]; ah[mt][3] = sAh[r1 + kw + 4];
                al[mt][0] = sAl[r0 + kw];     al[mt][1] = sAl[r1 + kw];
                al[mt][2] = sAl[r0 + kw + 4]; al[mt][3] = sAl[r1 + kw + 4];
            }
            #pragma unroll
            for (int nt = 0; nt < 8; nt++) {
                int nr = (n_base + nt * 8 + qr) * (SROW / 2);
                uint32_t bh0 = sWh[nr + kw], bh1 = sWh[nr + kw + 4];
                uint32_t bl0 = sWl[nr + kw], bl1 = sWl[nr + kw + 4];
                #pragma unroll
                for (int mt = 0; mt < 2; mt++) {
                    mma16816(acc[mt][nt], ah[mt][0], ah[mt][1], ah[mt][2], ah[mt][3], bh0, bh1);
                    mma16816(acc[mt][nt], ah[mt][0], ah[mt][1], ah[mt][2], ah[mt][3], bl0, bl1);
                    mma16816(acc[mt][nt], al[mt][0], al[mt][1], al[mt][2], al[mt][3], bh0, bh1);
                }
            }
        }
        __syncthreads();
    }

    // ---- epilogue: +bias, optional relu, optional *dinv[row] ----
    #pragma unroll
    for (int mt = 0; mt < 2; mt++) {
        int r0 = n0 + m_base + mt * 16 + qr;
        int r1 = r0 + 8;
        float d0 = 1.f, d1 = 1.f;
        if (SCALE) {
            d0 = (r0 < N_NODES) ? g_dinv[r0] : 0.f;
            d1 = (r1 < N_NODES) ? g_dinv[r1] : 0.f;
        }
        #pragma unroll
        for (int nt = 0; nt < 8; nt++) {
            int col = n_base + nt * 8 + qj * 2;
            float b0 = bias[col], b1 = bias[col + 1];
            if (r0 < N_NODES) {
                float vx = acc[mt][nt][0] + b0, vy = acc[mt][nt][1] + b1;
                if (RELU_OUT) { vx = fmaxf(vx, 0.f); vy = fmaxf(vy, 0.f); }
                if (SCALE)    { vx *= d0; vy *= d0; }
                *(float2*)(out + (size_t)r0 * D_OUT + col) = make_float2(vx, vy);
            }
            if (r1 < N_NODES) {
                float vx = acc[mt][nt][2] + b0, vy = acc[mt][nt][3] + b1;
                if (RELU_OUT) { vx = fmaxf(vx, 0.f); vy = fmaxf(vy, 0.f); }
                if (SCALE)    { vx *= d1; vy *= d1; }
                *(float2*)(out + (size_t)r1 * D_OUT + col) = make_float2(vx, vy);
            }
        }
    }
}

// ---------------- pure normalized aggregation (inputs prescaled by dinv) ----------------
// out[n] = dinv[n] * ( x[n] + sum_{s in in(n)} x[s] )
__global__ void k_agg(const float* __restrict__ x, float* __restrict__ out)
{
    int gw   = (blockIdx.x * blockDim.x + threadIdx.x) >> 5;
    int lane = threadIdx.x & 31;
    if (gw >= N_NODES) return;

    const float4* x4 = (const float4*)x;
    float4 acc = x4[gw * 32 + lane];          // self loop (prescaled)

    int b = g_off[gw], e = g_off[gw + 1];
    int i = b;
    for (; i + 4 <= e; i += 4) {
        int s0 = g_csr[i], s1 = g_csr[i+1], s2 = g_csr[i+2], s3 = g_csr[i+3];
        float4 v0 = x4[s0 * 32 + lane];
        float4 v1 = x4[s1 * 32 + lane];
        float4 v2 = x4[s2 * 32 + lane];
        float4 v3 = x4[s3 * 32 + lane];
        acc.x += (v0.x + v1.x) + (v2.x + v3.x);
        acc.y += (v0.y + v1.y) + (v2.y + v3.y);
        acc.z += (v0.z + v1.z) + (v2.z + v3.z);
        acc.w += (v0.w + v1.w) + (v2.w + v3.w);
    }
    for (; i < e; i++) {
        int s = g_csr[i];
        float4 v = x4[s * 32 + lane];
        acc.x += v.x; acc.y += v.y; acc.z += v.z; acc.w += v.w;
    }

    float di = g_dinv[gw];
    acc.x *= di; acc.y *= di; acc.z *= di; acc.w *= di;
    ((float4*)out)[gw * 32 + lane] = acc;
}

// ---------------- launch ----------------
extern "C" void kernel_launch(void* const* d_in, const int* in_sizes, int n_in,
                              void* d_out, int out_size)
{
    const int*   tokens = (const int*)  d_in[0];
    const int*   eidx   = (const int*)  d_in[1];
    const float* embed  = (const float*)d_in[2];
    const float* Wn     = (const float*)d_in[3];
    const float* Wb     = (const float*)d_in[4];
    const float* w1     = (const float*)d_in[5];
    const float* b1     = (const float*)d_in[6];
    const float* w2     = (const float*)d_in[7];
    const float* b2     = (const float*)d_in[8];
    float* out = (float*)d_out;

    const int* src = eidx;
    const int* dst = eidx + N_EDGES;

    float *xp, *yp, *hp;
    cudaGetSymbolAddress((void**)&xp, g_x);
    cudaGetSymbolAddress((void**)&yp, g_y);
    cudaGetSymbolAddress((void**)&hp, g_h);

    const int NB_N = (N_NODES + 255) / 256;
    const int NB_E = (N_EDGES + 255) / 256;
    const int NB_G = (N_NODES + 127) / 128;
    const int NB_C = (N_NODES * 32 + 255) / 256;

    // graph structure (dinv fused into scan1)
    k_zero <<<NB_N, 256>>>();
    k_count<<<NB_E, 256>>>(dst);
    k_scan1<<<NB_N, 256>>>();
    k_scan2<<<1,    256>>>(NB_N);
    k_scan3<<<NB_N, 256>>>();
    k_fill <<<NB_E, 256>>>(src, dst);

    // x' = (gather(embed) @ Wn^T + Wb) * dinv          [GEMM1, scale fused]
    k_gemm_mma<D_IN, true, false, true><<<NB_G, 256>>>(embed, tokens, Wn, Wb, xp);
    // z1 = dinv * (x'[self] + sum x'[nbr])             [agg1]
    k_agg<<<NB_C, 256>>>(xp, yp);
    // r' = relu(z1 @ w1^T + b1) * dinv                 [GEMM2, relu+scale fused]
    k_gemm_mma<D_OUT, false, true, true><<<NB_G, 256>>>(yp, nullptr, w1, b1, hp);
    // z2 = dinv * (r'[self] + sum r'[nbr])             [agg2]
    k_agg<<<NB_C, 256>>>(hp, yp);
    // out = z2 @ w2^T + b2                             [GEMM3]
    k_gemm_mma<D_OUT, false, false, false><<<NB_G, 256>>>(yp, nullptr, w2, b2, out);
}